// round 1
// baseline (speedup 1.0000x reference)
#include <cuda_runtime.h>
#include <math.h>
#include <stdint.h>

#define B_   8
#define L_   4096
#define D_   1024
#define H_   1024
#define LAT_ 256
#define KS_  32

// ---------------- device scratch (no allocations allowed) ----------------
__device__ float g_Scorr[B_ * KS_ * H_];
__device__ float g_Sdec [B_ * KS_ * H_];
__device__ float g_hT   [B_ * KS_ * H_];
__device__ float g_y    [B_ * KS_ * H_];
__device__ int   g_starts[B_ * KS_];
__device__ int   g_ends  [B_ * KS_];

// ---------------- kernel 0: segment bounds from bitmask ----------------
__global__ void k_bounds(const int* __restrict__ mask) {
    int b = blockIdx.x;
    int tid = threadIdx.x;
    const int CH = L_ / 256;  // 16 positions per thread
    __shared__ int cnt[256];
    __shared__ int base[256];

    const int* m = mask + (size_t)b * L_ + tid * CH;
    int c = 0;
#pragma unroll
    for (int i = 0; i < CH; i++) c += (m[i] != 0);
    cnt[tid] = c;
    __syncthreads();
    if (tid == 0) {
        int s = 0;
        for (int i = 0; i < 256; i++) { base[i] = s; s += cnt[i]; }
    }
    __syncthreads();
    int r = base[tid];
#pragma unroll
    for (int i = 0; i < CH; i++) {
        if (m[i] != 0) {
            if (r < KS_) g_ends[b * KS_ + r] = tid * CH + i + 1;  // exclusive end
            r++;
        }
    }
    __syncthreads();
    if (tid < KS_) g_starts[b * KS_ + tid] = (tid == 0) ? 0 : g_ends[b * KS_ + tid - 1];
}

// ---------------- kernel 1: fused projection GEMM + weighted segment reduce ----
// For block (n_tile, kseg, b*2+stream): computes
//   S[b,kseg,h] = sum_{t in [start,end)} a_h^(end-1-t) * (X[b,t,:] @ W[:,h] + bias_h)
// Tiles: M=128 (time rows), N=128 (h cols), K-step 8, 256 threads, 8x8 microtile.
#define TM  128
#define TN  128
#define TKK 8

__global__ __launch_bounds__(256, 2)
void k_proj_reduce(const float* __restrict__ Xtgt, const float* __restrict__ Xdec,
                   const float* __restrict__ W,    const float* __restrict__ bproj,
                   const float* __restrict__ araw)
{
    __shared__ float As[2][TKK][TM];
    __shared__ float Bs[2][TKK][TN];
    __shared__ float a_s[TN];
    __shared__ float bias_s[TN];
    __shared__ float red[16][TN];

    const int z      = blockIdx.z;
    const int b      = z >> 1;
    const int stream = z & 1;           // 0 -> targets (S_corr), 1 -> decoder (S_dec)
    const int kseg   = blockIdx.y;
    const int ht0    = blockIdx.x * TN;
    const float* __restrict__ X = stream ? Xdec : Xtgt;

    const int segs = g_starts[b * KS_ + kseg];
    const int sege = g_ends  [b * KS_ + kseg];

    const int tid = threadIdx.x;
    const int tx  = tid & 15;
    const int ty  = tid >> 4;

    if (tid < TN) {
        float ar = araw[ht0 + tid];
        a_s[tid]    = 1.0f / (1.0f + expf(-ar));
        bias_s[tid] = bproj[ht0 + tid];
    }
    __syncthreads();

    // per-thread column constants
    float l2a[8], bj[8];
#pragma unroll
    for (int j = 0; j < 8; j++) {
        int c = (j < 4) ? (tx * 4 + j) : (64 + tx * 4 + (j - 4));
        l2a[j] = log2f(a_s[c]);
        bj[j]  = bias_s[c];
    }

    float partial[8];
#pragma unroll
    for (int j = 0; j < 8; j++) partial[j] = 0.0f;

    // load-index precompute
    const int arow = tid >> 1;          // 0..127
    const int akq  = (tid & 1) * 4;     // 0 or 4
    const int bkk  = tid >> 5;          // 0..7
    const int bh4  = (tid & 31) * 4;    // 0..124

    for (int cs = segs; cs < sege; cs += TM) {
        float acc[8][8];
#pragma unroll
        for (int i = 0; i < 8; i++)
#pragma unroll
            for (int j = 0; j < 8; j++) acc[i][j] = 0.0f;

        const int t0 = cs + arow;
        const bool rowok = (t0 < sege);
        const float* __restrict__ Xrow = X + ((size_t)b * L_ + t0) * D_ + akq;

        // preload first tiles (kt = 0)
        float4 va = make_float4(0.f, 0.f, 0.f, 0.f);
        if (rowok) va = *reinterpret_cast<const float4*>(Xrow);
        float4 vb = *reinterpret_cast<const float4*>(W + (size_t)bkk * H_ + ht0 + bh4);

        As[0][akq + 0][arow] = va.x;
        As[0][akq + 1][arow] = va.y;
        As[0][akq + 2][arow] = va.z;
        As[0][akq + 3][arow] = va.w;
        *reinterpret_cast<float4*>(&Bs[0][bkk][bh4]) = vb;
        __syncthreads();

        int buf = 0;
        for (int kt = 0; kt < D_; kt += TKK) {
            // prefetch next K-slab into registers
            float4 pa = make_float4(0.f, 0.f, 0.f, 0.f), pb;
            const bool more = (kt + TKK) < D_;
            if (more) {
                if (rowok) pa = *reinterpret_cast<const float4*>(Xrow + kt + TKK);
                pb = *reinterpret_cast<const float4*>(
                        W + (size_t)(kt + TKK + bkk) * H_ + ht0 + bh4);
            }
            // compute on current buffer
#pragma unroll
            for (int kk = 0; kk < TKK; kk++) {
                float af[8], bf[8];
                *reinterpret_cast<float4*>(&af[0]) =
                    *reinterpret_cast<const float4*>(&As[buf][kk][ty * 4]);
                *reinterpret_cast<float4*>(&af[4]) =
                    *reinterpret_cast<const float4*>(&As[buf][kk][64 + ty * 4]);
                *reinterpret_cast<float4*>(&bf[0]) =
                    *reinterpret_cast<const float4*>(&Bs[buf][kk][tx * 4]);
                *reinterpret_cast<float4*>(&bf[4]) =
                    *reinterpret_cast<const float4*>(&Bs[buf][kk][64 + tx * 4]);
#pragma unroll
                for (int i = 0; i < 8; i++)
#pragma unroll
                    for (int j = 0; j < 8; j++)
                        acc[i][j] = fmaf(af[i], bf[j], acc[i][j]);
            }
            if (more) {
                const int wb = buf ^ 1;
                As[wb][akq + 0][arow] = pa.x;
                As[wb][akq + 1][arow] = pa.y;
                As[wb][akq + 2][arow] = pa.z;
                As[wb][akq + 3][arow] = pa.w;
                *reinterpret_cast<float4*>(&Bs[wb][bkk][bh4]) = pb;
            }
            __syncthreads();
            buf ^= 1;
        }

        // epilogue: weighted reduce over this chunk's rows (weights a^(end-1-t))
#pragma unroll
        for (int j = 0; j < 8; j++) {
            const float lj = l2a[j];
            const float bb = bj[j];
#pragma unroll
            for (int i = 0; i < 8; i++) {
                const int r = (i < 4) ? (ty * 4 + i) : (64 + ty * 4 + (i - 4));
                const int p = sege - 1 - (cs + r);
                if (p >= 0) {
                    float w = exp2f((float)p * lj);
                    partial[j] = fmaf(w, acc[i][j] + bb, partial[j]);
                }
            }
        }
    }

    // cross-thread reduction over the 16 row groups
#pragma unroll
    for (int j = 0; j < 8; j++) {
        int c = (j < 4) ? (tx * 4 + j) : (64 + tx * 4 + (j - 4));
        red[ty][c] = partial[j];
    }
    __syncthreads();
    if (tid < TN) {
        float s = 0.0f;
#pragma unroll
        for (int i = 0; i < 16; i++) s += red[i][tid];
        float* g = stream ? g_Sdec : g_Scorr;
        g[((size_t)(b * KS_ + kseg)) * H_ + ht0 + tid] = s;
    }
}

// ---------------- kernel 2: K-step prefix scan over segments ----------------
__global__ void k_scan(const float* __restrict__ araw) {
    int idx = blockIdx.x * blockDim.x + threadIdx.x;
    if (idx >= B_ * H_) return;
    int b = idx / H_;
    int h = idx % H_;
    float a   = 1.0f / (1.0f + expf(-araw[h]));
    float l2a = log2f(a);
    float hp = 0.0f;
    for (int k = 0; k < KS_; k++) {
        int len = g_ends[b * KS_ + k] - g_starts[b * KS_ + k];
        float ap = exp2f((float)len * l2a);
        size_t o = (size_t)(b * KS_ + k) * H_ + h;
        g_hT[o] = fmaf(ap, hp, g_Sdec[o]);
        hp      = fmaf(ap, hp, g_Scorr[o]);
    }
}

// ---------------- kernel 3: small GEMM (+bias, optional SiLU) ----------------
// C[M,N] = A[M,K] @ Bm[K,N] + bias ; tile 32x64, BK=32, 256 threads, 4x2 micro.
template <bool SILU>
__global__ void k_gemm_small(const float* __restrict__ A, const float* __restrict__ Bm,
                             const float* __restrict__ bias, float* __restrict__ C,
                             int M, int N, int Kd)
{
    __shared__ float Asm[32][36];
    __shared__ float Bsm[32][64];

    const int n0 = blockIdx.x * 64;
    const int m0 = blockIdx.y * 32;
    const int tid = threadIdx.x;
    const int r0 = (tid >> 5) * 4;
    const int c0 = (tid & 31) * 2;

    float acc[4][2];
#pragma unroll
    for (int i = 0; i < 4; i++) { acc[i][0] = 0.f; acc[i][1] = 0.f; }

    const int lam = tid >> 3;          // 0..31 row
    const int lak = (tid & 7) * 4;     // k offset

    for (int kt = 0; kt < Kd; kt += 32) {
        float4 va = *reinterpret_cast<const float4*>(A + (size_t)(m0 + lam) * Kd + kt + lak);
        Asm[lak + 0][lam] = va.x;
        Asm[lak + 1][lam] = va.y;
        Asm[lak + 2][lam] = va.z;
        Asm[lak + 3][lam] = va.w;
#pragma unroll
        for (int q = 0; q < 2; q++) {
            int e  = tid + q * 256;
            int kk = e >> 4;
            int c4 = (e & 15) * 4;
            *reinterpret_cast<float4*>(&Bsm[kk][c4]) =
                *reinterpret_cast<const float4*>(Bm + (size_t)(kt + kk) * N + n0 + c4);
        }
        __syncthreads();
#pragma unroll
        for (int kk = 0; kk < 32; kk++) {
            float a0 = Asm[kk][r0 + 0];
            float a1 = Asm[kk][r0 + 1];
            float a2 = Asm[kk][r0 + 2];
            float a3 = Asm[kk][r0 + 3];
            float b0 = Bsm[kk][c0 + 0];
            float b1 = Bsm[kk][c0 + 1];
            acc[0][0] = fmaf(a0, b0, acc[0][0]); acc[0][1] = fmaf(a0, b1, acc[0][1]);
            acc[1][0] = fmaf(a1, b0, acc[1][0]); acc[1][1] = fmaf(a1, b1, acc[1][1]);
            acc[2][0] = fmaf(a2, b0, acc[2][0]); acc[2][1] = fmaf(a2, b1, acc[2][1]);
            acc[3][0] = fmaf(a3, b0, acc[3][0]); acc[3][1] = fmaf(a3, b1, acc[3][1]);
        }
        __syncthreads();
    }

#pragma unroll
    for (int i = 0; i < 4; i++)
#pragma unroll
        for (int j = 0; j < 2; j++) {
            int row = m0 + r0 + i;
            int col = n0 + c0 + j;
            float v = acc[i][j] + bias[col];
            if (SILU) v = v / (1.0f + expf(-v));   // x * sigmoid(x)
            C[(size_t)row * N + col] = v;
        }
}

// ---------------- launcher ----------------
extern "C" void kernel_launch(void* const* d_in, const int* in_sizes, int n_in,
                              void* d_out, int out_size) {
    (void)in_sizes; (void)n_in; (void)out_size;

    const float* dec   = (const float*)d_in[0];   // decoder_output (B,L,D)
    const float* tgt   = (const float*)d_in[1];   // targets        (B,L,D)
    const float* Wp    = (const float*)d_in[2];   // W_proj (D,H)
    const float* bp    = (const float*)d_in[3];   // b_proj (H)
    const float* araw  = (const float*)d_in[4];   // a_raw  (H)
    const float* Wout  = (const float*)d_in[5];   // W_out  (H,H)
    const float* bout  = (const float*)d_in[6];   // b_out  (H)
    const float* Wmu   = (const float*)d_in[7];   // W_mu   (H,LAT)
    const float* bmu   = (const float*)d_in[8];   // b_mu   (LAT)
    const float* Wlv   = (const float*)d_in[9];   // W_lv   (H,LAT)
    const float* blv   = (const float*)d_in[10];  // b_lv   (LAT)
    const int*   mask  = (const int*)  d_in[11];  // segmentation_indices (B,L)
    // d_in[12] = num_subseq (unused; K fixed by shapes)

    float* out = (float*)d_out;                   // [mu (B,K,LAT) | logvar (B,K,LAT)]

    void *pHT = nullptr, *pY = nullptr;
    cudaGetSymbolAddress(&pHT, g_hT);
    cudaGetSymbolAddress(&pY,  g_y);

    // 0) segment bounds
    k_bounds<<<B_, 256>>>(mask);

    // 1) fused projection + weighted segment reduction (both streams)
    dim3 g1(H_ / TN, KS_, B_ * 2);
    k_proj_reduce<<<g1, 256>>>(tgt, dec, Wp, bp, araw);

    // 2) 32-step segment scan -> hT
    k_scan<<<(B_ * H_) / 256, 256>>>(araw);

    // 3) heads: y = silu(hT @ W_out + b_out); mu = y @ W_mu + b_mu; lv = y @ W_lv + b_lv
    k_gemm_small<true ><<<dim3(H_ / 64,  (B_ * KS_) / 32), 256>>>(
        (const float*)pHT, Wout, bout, (float*)pY, B_ * KS_, H_, H_);
    k_gemm_small<false><<<dim3(LAT_ / 64, (B_ * KS_) / 32), 256>>>(
        (const float*)pY, Wmu, bmu, out, B_ * KS_, LAT_, H_);
    k_gemm_small<false><<<dim3(LAT_ / 64, (B_ * KS_) / 32), 256>>>(
        (const float*)pY, Wlv, blv, out + (size_t)B_ * KS_ * LAT_, B_ * KS_, LAT_, H_);
}

// round 2
// speedup vs baseline: 1.0027x; 1.0027x over previous
#include <cuda_runtime.h>
#include <math.h>
#include <stdint.h>

#define B_   8
#define L_   4096
#define D_   1024
#define H_   1024
#define LAT_ 256
#define KS_  32

// ---------------- device scratch (no allocations allowed) ----------------
__device__ float g_Scorr[B_ * KS_ * H_];
__device__ float g_Sdec [B_ * KS_ * H_];
__device__ float g_hT   [B_ * KS_ * H_];
__device__ float g_y    [B_ * KS_ * H_];
__device__ int   g_starts[B_ * KS_];
__device__ int   g_ends  [B_ * KS_];

// ---------------- kernel 0: segment bounds from bitmask ----------------
__global__ void k_bounds(const int* __restrict__ mask) {
    int b = blockIdx.x;
    int tid = threadIdx.x;
    const int CH = L_ / 256;  // 16 positions per thread
    __shared__ int cnt[256];
    __shared__ int base[256];

    const int* m = mask + (size_t)b * L_ + tid * CH;
    int c = 0;
#pragma unroll
    for (int i = 0; i < CH; i++) c += (m[i] != 0);
    cnt[tid] = c;
    __syncthreads();
    if (tid == 0) {
        int s = 0;
        for (int i = 0; i < 256; i++) { base[i] = s; s += cnt[i]; }
    }
    __syncthreads();
    int r = base[tid];
#pragma unroll
    for (int i = 0; i < CH; i++) {
        if (m[i] != 0) {
            if (r < KS_) g_ends[b * KS_ + r] = tid * CH + i + 1;  // exclusive end
            r++;
        }
    }
    __syncthreads();
    if (tid < KS_) g_starts[b * KS_ + tid] = (tid == 0) ? 0 : g_ends[b * KS_ + tid - 1];
}

// ---------------- kernel 1: fused projection GEMM + weighted segment reduce ----
// For block (n_tile, kseg, b*2+stream): computes
//   S[b,kseg,h] = sum_{t in [start,end)} a_h^(end-1-t) * (X[b,t,:] @ W[:,h] + bias_h)
// Tiles: M=128 (time rows), N=128 (h cols), K-step 8, 256 threads, 8x8 microtile.
#define TM  128
#define TN  128
#define TKK 8

__global__ __launch_bounds__(256, 2)
void k_proj_reduce(const float* __restrict__ Xtgt, const float* __restrict__ Xdec,
                   const float* __restrict__ W,    const float* __restrict__ bproj,
                   const float* __restrict__ araw)
{
    __shared__ float As[2][TKK][TM];
    __shared__ float Bs[2][TKK][TN];
    __shared__ float a_s[TN];
    __shared__ float bias_s[TN];
    __shared__ float red[16][TN];

    const int z      = blockIdx.z;
    const int b      = z >> 1;
    const int stream = z & 1;           // 0 -> targets (S_corr), 1 -> decoder (S_dec)
    const int kseg   = blockIdx.y;
    const int ht0    = blockIdx.x * TN;
    const float* __restrict__ X = stream ? Xdec : Xtgt;

    const int segs = g_starts[b * KS_ + kseg];
    const int sege = g_ends  [b * KS_ + kseg];

    const int tid = threadIdx.x;
    const int tx  = tid & 15;
    const int ty  = tid >> 4;

    if (tid < TN) {
        float ar = araw[ht0 + tid];
        a_s[tid]    = 1.0f / (1.0f + expf(-ar));
        bias_s[tid] = bproj[ht0 + tid];
    }
    __syncthreads();

    // per-thread column constants
    float l2a[8], bj[8];
#pragma unroll
    for (int j = 0; j < 8; j++) {
        int c = (j < 4) ? (tx * 4 + j) : (64 + tx * 4 + (j - 4));
        l2a[j] = log2f(a_s[c]);
        bj[j]  = bias_s[c];
    }

    float partial[8];
#pragma unroll
    for (int j = 0; j < 8; j++) partial[j] = 0.0f;

    // load-index precompute
    const int arow = tid >> 1;          // 0..127
    const int akq  = (tid & 1) * 4;     // 0 or 4
    const int bkk  = tid >> 5;          // 0..7
    const int bh4  = (tid & 31) * 4;    // 0..124

    for (int cs = segs; cs < sege; cs += TM) {
        float acc[8][8];
#pragma unroll
        for (int i = 0; i < 8; i++)
#pragma unroll
            for (int j = 0; j < 8; j++) acc[i][j] = 0.0f;

        const int t0 = cs + arow;
        const bool rowok = (t0 < sege);
        const float* __restrict__ Xrow = X + ((size_t)b * L_ + t0) * D_ + akq;

        // preload first tiles (kt = 0)
        float4 va = make_float4(0.f, 0.f, 0.f, 0.f);
        if (rowok) va = *reinterpret_cast<const float4*>(Xrow);
        float4 vb = *reinterpret_cast<const float4*>(W + (size_t)bkk * H_ + ht0 + bh4);

        As[0][akq + 0][arow] = va.x;
        As[0][akq + 1][arow] = va.y;
        As[0][akq + 2][arow] = va.z;
        As[0][akq + 3][arow] = va.w;
        *reinterpret_cast<float4*>(&Bs[0][bkk][bh4]) = vb;
        __syncthreads();

        int buf = 0;
        for (int kt = 0; kt < D_; kt += TKK) {
            // prefetch next K-slab into registers
            float4 pa = make_float4(0.f, 0.f, 0.f, 0.f), pb;
            const bool more = (kt + TKK) < D_;
            if (more) {
                if (rowok) pa = *reinterpret_cast<const float4*>(Xrow + kt + TKK);
                pb = *reinterpret_cast<const float4*>(
                        W + (size_t)(kt + TKK + bkk) * H_ + ht0 + bh4);
            }
            // compute on current buffer
#pragma unroll
            for (int kk = 0; kk < TKK; kk++) {
                float af[8], bf[8];
                *reinterpret_cast<float4*>(&af[0]) =
                    *reinterpret_cast<const float4*>(&As[buf][kk][ty * 4]);
                *reinterpret_cast<float4*>(&af[4]) =
                    *reinterpret_cast<const float4*>(&As[buf][kk][64 + ty * 4]);
                *reinterpret_cast<float4*>(&bf[0]) =
                    *reinterpret_cast<const float4*>(&Bs[buf][kk][tx * 4]);
                *reinterpret_cast<float4*>(&bf[4]) =
                    *reinterpret_cast<const float4*>(&Bs[buf][kk][64 + tx * 4]);
#pragma unroll
                for (int i = 0; i < 8; i++)
#pragma unroll
                    for (int j = 0; j < 8; j++)
                        acc[i][j] = fmaf(af[i], bf[j], acc[i][j]);
            }
            if (more) {
                const int wb = buf ^ 1;
                As[wb][akq + 0][arow] = pa.x;
                As[wb][akq + 1][arow] = pa.y;
                As[wb][akq + 2][arow] = pa.z;
                As[wb][akq + 3][arow] = pa.w;
                *reinterpret_cast<float4*>(&Bs[wb][bkk][bh4]) = pb;
            }
            __syncthreads();
            buf ^= 1;
        }

        // epilogue: weighted reduce over this chunk's rows (weights a^(end-1-t))
#pragma unroll
        for (int j = 0; j < 8; j++) {
            const float lj = l2a[j];
            const float bb = bj[j];
#pragma unroll
            for (int i = 0; i < 8; i++) {
                const int r = (i < 4) ? (ty * 4 + i) : (64 + ty * 4 + (i - 4));
                const int p = sege - 1 - (cs + r);
                if (p >= 0) {
                    float w = exp2f((float)p * lj);
                    partial[j] = fmaf(w, acc[i][j] + bb, partial[j]);
                }
            }
        }
    }

    // cross-thread reduction over the 16 row groups
#pragma unroll
    for (int j = 0; j < 8; j++) {
        int c = (j < 4) ? (tx * 4 + j) : (64 + tx * 4 + (j - 4));
        red[ty][c] = partial[j];
    }
    __syncthreads();
    if (tid < TN) {
        float s = 0.0f;
#pragma unroll
        for (int i = 0; i < 16; i++) s += red[i][tid];
        float* g = stream ? g_Sdec : g_Scorr;
        g[((size_t)(b * KS_ + kseg)) * H_ + ht0 + tid] = s;
    }
}

// ---------------- kernel 2: K-step prefix scan over segments ----------------
__global__ void k_scan(const float* __restrict__ araw) {
    int idx = blockIdx.x * blockDim.x + threadIdx.x;
    if (idx >= B_ * H_) return;
    int b = idx / H_;
    int h = idx % H_;
    float a   = 1.0f / (1.0f + expf(-araw[h]));
    float l2a = log2f(a);
    float hp = 0.0f;
    for (int k = 0; k < KS_; k++) {
        int len = g_ends[b * KS_ + k] - g_starts[b * KS_ + k];
        float ap = exp2f((float)len * l2a);
        size_t o = (size_t)(b * KS_ + k) * H_ + h;
        g_hT[o] = fmaf(ap, hp, g_Sdec[o]);
        hp      = fmaf(ap, hp, g_Scorr[o]);
    }
}

// ---------------- kernel 3: small GEMM (+bias, optional SiLU) ----------------
// C[M,N] = A[M,K] @ Bm[K,N] + bias ; tile 32x64, BK=32, 256 threads, 4x2 micro.
template <bool SILU>
__global__ void k_gemm_small(const float* __restrict__ A, const float* __restrict__ Bm,
                             const float* __restrict__ bias, float* __restrict__ C,
                             int M, int N, int Kd)
{
    __shared__ float Asm[32][36];
    __shared__ float Bsm[32][64];

    const int n0 = blockIdx.x * 64;
    const int m0 = blockIdx.y * 32;
    const int tid = threadIdx.x;
    const int r0 = (tid >> 5) * 4;
    const int c0 = (tid & 31) * 2;

    float acc[4][2];
#pragma unroll
    for (int i = 0; i < 4; i++) { acc[i][0] = 0.f; acc[i][1] = 0.f; }

    const int lam = tid >> 3;          // 0..31 row
    const int lak = (tid & 7) * 4;     // k offset

    for (int kt = 0; kt < Kd; kt += 32) {
        float4 va = *reinterpret_cast<const float4*>(A + (size_t)(m0 + lam) * Kd + kt + lak);
        Asm[lak + 0][lam] = va.x;
        Asm[lak + 1][lam] = va.y;
        Asm[lak + 2][lam] = va.z;
        Asm[lak + 3][lam] = va.w;
#pragma unroll
        for (int q = 0; q < 2; q++) {
            int e  = tid + q * 256;
            int kk = e >> 4;
            int c4 = (e & 15) * 4;
            *reinterpret_cast<float4*>(&Bsm[kk][c4]) =
                *reinterpret_cast<const float4*>(Bm + (size_t)(kt + kk) * N + n0 + c4);
        }
        __syncthreads();
#pragma unroll
        for (int kk = 0; kk < 32; kk++) {
            float a0 = Asm[kk][r0 + 0];
            float a1 = Asm[kk][r0 + 1];
            float a2 = Asm[kk][r0 + 2];
            float a3 = Asm[kk][r0 + 3];
            float b0 = Bsm[kk][c0 + 0];
            float b1 = Bsm[kk][c0 + 1];
            acc[0][0] = fmaf(a0, b0, acc[0][0]); acc[0][1] = fmaf(a0, b1, acc[0][1]);
            acc[1][0] = fmaf(a1, b0, acc[1][0]); acc[1][1] = fmaf(a1, b1, acc[1][1]);
            acc[2][0] = fmaf(a2, b0, acc[2][0]); acc[2][1] = fmaf(a2, b1, acc[2][1]);
            acc[3][0] = fmaf(a3, b0, acc[3][0]); acc[3][1] = fmaf(a3, b1, acc[3][1]);
        }
        __syncthreads();
    }

#pragma unroll
    for (int i = 0; i < 4; i++)
#pragma unroll
        for (int j = 0; j < 2; j++) {
            int row = m0 + r0 + i;
            int col = n0 + c0 + j;
            float v = acc[i][j] + bias[col];
            if (SILU) v = v / (1.0f + expf(-v));   // x * sigmoid(x)
            C[(size_t)row * N + col] = v;
        }
}

// ---------------- launcher ----------------
extern "C" void kernel_launch(void* const* d_in, const int* in_sizes, int n_in,
                              void* d_out, int out_size) {
    (void)in_sizes; (void)n_in; (void)out_size;

    const float* dec   = (const float*)d_in[0];   // decoder_output (B,L,D)
    const float* tgt   = (const float*)d_in[1];   // targets        (B,L,D)
    const float* Wp    = (const float*)d_in[2];   // W_proj (D,H)
    const float* bp    = (const float*)d_in[3];   // b_proj (H)
    const float* araw  = (const float*)d_in[4];   // a_raw  (H)
    const float* Wout  = (const float*)d_in[5];   // W_out  (H,H)
    const float* bout  = (const float*)d_in[6];   // b_out  (H)
    const float* Wmu   = (const float*)d_in[7];   // W_mu   (H,LAT)
    const float* bmu   = (const float*)d_in[8];   // b_mu   (LAT)
    const float* Wlv   = (const float*)d_in[9];   // W_lv   (H,LAT)
    const float* blv   = (const float*)d_in[10];  // b_lv   (LAT)
    const int*   mask  = (const int*)  d_in[11];  // segmentation_indices (B,L)
    // d_in[12] = num_subseq (unused; K fixed by shapes)

    float* out = (float*)d_out;                   // [mu (B,K,LAT) | logvar (B,K,LAT)]

    void *pHT = nullptr, *pY = nullptr;
    cudaGetSymbolAddress(&pHT, g_hT);
    cudaGetSymbolAddress(&pY,  g_y);

    // 0) segment bounds
    k_bounds<<<B_, 256>>>(mask);

    // 1) fused projection + weighted segment reduction (both streams)
    dim3 g1(H_ / TN, KS_, B_ * 2);
    k_proj_reduce<<<g1, 256>>>(tgt, dec, Wp, bp, araw);

    // 2) 32-step segment scan -> hT
    k_scan<<<(B_ * H_) / 256, 256>>>(araw);

    // 3) heads: y = silu(hT @ W_out + b_out); mu = y @ W_mu + b_mu; lv = y @ W_lv + b_lv
    k_gemm_small<true ><<<dim3(H_ / 64,  (B_ * KS_) / 32), 256>>>(
        (const float*)pHT, Wout, bout, (float*)pY, B_ * KS_, H_, H_);
    k_gemm_small<false><<<dim3(LAT_ / 64, (B_ * KS_) / 32), 256>>>(
        (const float*)pY, Wmu, bmu, out, B_ * KS_, LAT_, H_);
    k_gemm_small<false><<<dim3(LAT_ / 64, (B_ * KS_) / 32), 256>>>(
        (const float*)pY, Wlv, blv, out + (size_t)B_ * KS_ * LAT_, B_ * KS_, LAT_, H_);
}

// round 4
// speedup vs baseline: 3.2896x; 3.2808x over previous
#include <cuda_runtime.h>
#include <cuda_fp16.h>
#include <math.h>
#include <stdint.h>

#define B_   8
#define L_   4096
#define D_   1024
#define H_   1024
#define LAT_ 256
#define KS_  32
#define TM_  128
#define TN_  128
#define BK_  32
#define NCH  (D_ / BK_)   // 32 chunks

// SMEM tile pitch: 40 fp16 = 80 bytes (conflict-free, 8B/16B aligned rows)
#define PXB  80
#define SZST 10240        // 128 rows * 80 B, one stage of one tile
#define OFF_XHI 0
#define OFF_XLO 20480
#define OFF_W   40960
#define OFF_L2A 61440
#define OFF_BIA 61952
#define OFF_ACC 62464
#define SMEM_DYN 62976

__device__ float g_Scorr[B_ * KS_ * H_];
__device__ float g_Sdec [B_ * KS_ * H_];
__device__ float g_hT   [B_ * KS_ * H_];
__device__ float g_y    [B_ * KS_ * H_];
__device__ int   g_starts[B_ * KS_];
__device__ int   g_ends  [B_ * KS_];
__device__ __half g_Wf16[H_ * D_];      // W^T as fp16: [n][k]

// ---------- helpers ----------
__device__ __forceinline__ uint32_t smem_u32(const void* p) {
    uint32_t a;
    asm("{ .reg .u64 t; cvta.to.shared.u64 t, %1; cvt.u32.u64 %0, t; }" : "=r"(a) : "l"(p));
    return a;
}
__device__ __forceinline__ uint32_t lds32(uint32_t a) {
    uint32_t v;
    asm volatile("ld.shared.b32 %0, [%1];" : "=r"(v) : "r"(a));
    return v;
}
__device__ __forceinline__ void sts_v2(uint32_t a, uint32_t x, uint32_t y) {
    asm volatile("st.shared.v2.b32 [%0], {%1,%2};" :: "r"(a), "r"(x), "r"(y));
}
__device__ __forceinline__ void cpa16(uint32_t s, const void* g) {
    unsigned long long gg = (unsigned long long)__cvta_generic_to_global(g);
    asm volatile("cp.async.cg.shared.global [%0], [%1], 16;" :: "r"(s), "l"(gg));
}
__device__ __forceinline__ void hmma(float* c, uint32_t a0, uint32_t a1, uint32_t a2,
                                     uint32_t a3, uint32_t b0, uint32_t b1) {
    asm volatile(
        "mma.sync.aligned.m16n8k16.row.col.f32.f16.f16.f32 "
        "{%0,%1,%2,%3}, {%4,%5,%6,%7}, {%8,%9}, {%0,%1,%2,%3};"
        : "+f"(c[0]), "+f"(c[1]), "+f"(c[2]), "+f"(c[3])
        : "r"(a0), "r"(a1), "r"(a2), "r"(a3), "r"(b0), "r"(b1));
}
__device__ __forceinline__ uint32_t pkh(__half a, __half b) {
    return (uint32_t)__half_as_ushort(a) | ((uint32_t)__half_as_ushort(b) << 16);
}

// ---------- kernel 0: segment bounds ----------
__global__ void k_bounds(const int* __restrict__ mask) {
    int b = blockIdx.x, tid = threadIdx.x;
    const int CH = L_ / 256;
    __shared__ int cnt[256], base[256];
    const int* m = mask + (size_t)b * L_ + tid * CH;
    int c = 0;
#pragma unroll
    for (int i = 0; i < CH; i++) c += (m[i] != 0);
    cnt[tid] = c;
    __syncthreads();
    if (tid == 0) { int s = 0; for (int i = 0; i < 256; i++) { base[i] = s; s += cnt[i]; } }
    __syncthreads();
    int r = base[tid];
#pragma unroll
    for (int i = 0; i < CH; i++)
        if (m[i] != 0) { if (r < KS_) g_ends[b * KS_ + r] = tid * CH + i + 1; r++; }
    __syncthreads();
    if (tid < KS_) g_starts[b * KS_ + tid] = (tid == 0) ? 0 : g_ends[b * KS_ + tid - 1];
}

// ---------- kernel 0b: W transpose + fp16 ----------
__global__ void k_prepW(const float* __restrict__ W) {     // W[k][n] -> g_Wf16[n][k]
    __shared__ float t[32][33];
    int n0 = blockIdx.x * 32, k0 = blockIdx.y * 32;
    for (int i = threadIdx.y; i < 32; i += 8)
        t[i][threadIdx.x] = W[(size_t)(k0 + i) * H_ + n0 + threadIdx.x];
    __syncthreads();
    for (int i = threadIdx.y; i < 32; i += 8)
        g_Wf16[(size_t)(n0 + i) * D_ + (k0 + threadIdx.x)] = __float2half_rn(t[threadIdx.x][i]);
}

// ---------- kernel 1: HMMA fused GEMM + weighted segment reduce ----------
__global__ __launch_bounds__(256, 2)
void k_mma(const float* __restrict__ Xtgt, const float* __restrict__ Xdec,
           const float* __restrict__ bproj, const float* __restrict__ araw) {
    extern __shared__ char smem[];
    const uint32_t sb = smem_u32(smem);

    const int tid = threadIdx.x, wid = tid >> 5, lane = tid & 31;
    const int wm = wid >> 2, wn = wid & 3;              // warp grid 2(M) x 4(N)
    const int z = blockIdx.z, b = z >> 1, stream = z & 1;
    const int kseg = blockIdx.y, ht0 = blockIdx.x * TN_;
    const float* __restrict__ Xb =
        (stream ? Xdec : Xtgt) + (size_t)b * L_ * D_;
    const int segs = g_starts[b * KS_ + kseg];
    const int sege = g_ends  [b * KS_ + kseg];

    float* l2a_s  = (float*)(smem + OFF_L2A);
    float* bias_s = (float*)(smem + OFF_BIA);
    float* acc_s  = (float*)(smem + OFF_ACC);
    if (tid < TN_) {
        float a = 1.0f / (1.0f + expf(-araw[ht0 + tid]));
        l2a_s[tid]  = log2f(a);
        bias_s[tid] = bproj[ht0 + tid];
        acc_s[tid]  = 0.0f;
    }
    __syncthreads();

    // per-thread load indices
    const int xrow = tid >> 3, xf4 = tid & 7;           // X: 8 float4 per row
    const int lrow = lane >> 2, lk2 = (lane & 3) * 2;   // fragment lane mapping

    for (int cs = segs; cs < sege; cs += TM_) {
        float acc[4][4][4];
#pragma unroll
        for (int i = 0; i < 4; i++)
#pragma unroll
            for (int j = 0; j < 4; j++)
#pragma unroll
                for (int q = 0; q < 4; q++) acc[i][j][q] = 0.0f;

        // ---- load chunk 0 into stage 0 ----
        {
#pragma unroll
            for (int q = 0; q < 4; q++) {
                int row = xrow + q * 32;
                int t = cs + row;
                float4 v = make_float4(0.f, 0.f, 0.f, 0.f);
                if (t < sege) v = *(const float4*)(Xb + (size_t)t * D_ + xf4 * 4);
                __half hx = __float2half_rn(v.x), hy = __float2half_rn(v.y);
                __half hz = __float2half_rn(v.z), hw = __float2half_rn(v.w);
                __half lx = __float2half_rn(v.x - __half2float(hx));
                __half ly = __float2half_rn(v.y - __half2float(hy));
                __half lz = __float2half_rn(v.z - __half2float(hz));
                __half lw = __float2half_rn(v.w - __half2float(hw));
                uint32_t off = row * PXB + xf4 * 8;
                sts_v2(sb + OFF_XHI + off, pkh(hx, hy), pkh(hz, hw));
                sts_v2(sb + OFF_XLO + off, pkh(lx, ly), pkh(lz, lw));
            }
#pragma unroll
            for (int q = 0; q < 2; q++) {
                int idx = tid + q * 256;
                int row = idx >> 2, sg = idx & 3;
                cpa16(sb + OFF_W + row * PXB + sg * 16,
                      g_Wf16 + (size_t)(ht0 + row) * D_ + sg * 8);
            }
            asm volatile("cp.async.commit_group;");
            asm volatile("cp.async.wait_group 0;" ::: "memory");
            __syncthreads();
        }

#pragma unroll 1
        for (int c = 0; c < NCH; c++) {
            const int cur = c & 1, nxt = cur ^ 1;
            const bool more = (c + 1 < NCH);

            // prefetch next chunk: X -> regs, W -> cp.async
            float4 px[4];
            if (more) {
                const int kt = (c + 1) * BK_;
#pragma unroll
                for (int q = 0; q < 4; q++) {
                    int row = xrow + q * 32;
                    int t = cs + row;
                    px[q] = make_float4(0.f, 0.f, 0.f, 0.f);
                    if (t < sege) px[q] = *(const float4*)(Xb + (size_t)t * D_ + kt + xf4 * 4);
                }
#pragma unroll
                for (int q = 0; q < 2; q++) {
                    int idx = tid + q * 256;
                    int row = idx >> 2, sg = idx & 3;
                    cpa16(sb + OFF_W + nxt * SZST + row * PXB + sg * 16,
                          g_Wf16 + (size_t)(ht0 + row) * D_ + kt + sg * 8);
                }
                asm volatile("cp.async.commit_group;");
            }

            // ---- compute current chunk (2 k16 steps) ----
            const uint32_t xh = sb + OFF_XHI + cur * SZST;
            const uint32_t xl = sb + OFF_XLO + cur * SZST;
            const uint32_t wb = sb + OFF_W   + cur * SZST;
#pragma unroll
            for (int ks = 0; ks < 2; ks++) {
                const int kofs = (ks * 16 + lk2) * 2;
                uint32_t b0[4], b1[4];
#pragma unroll
                for (int nt = 0; nt < 4; nt++) {
                    uint32_t ba = wb + (wn * 32 + nt * 8 + lrow) * PXB + kofs;
                    b0[nt] = lds32(ba);
                    b1[nt] = lds32(ba + 16);
                }
#pragma unroll
                for (int mt = 0; mt < 4; mt++) {
                    uint32_t aa = xh + (wm * 64 + mt * 16 + lrow) * PXB + kofs;
                    uint32_t a0 = lds32(aa),           a1 = lds32(aa + 8 * PXB);
                    uint32_t a2 = lds32(aa + 16),      a3 = lds32(aa + 8 * PXB + 16);
                    uint32_t la = xl + (wm * 64 + mt * 16 + lrow) * PXB + kofs;
                    uint32_t l0 = lds32(la),           l1 = lds32(la + 8 * PXB);
                    uint32_t l2 = lds32(la + 16),      l3 = lds32(la + 8 * PXB + 16);
#pragma unroll
                    for (int nt = 0; nt < 4; nt++) {
                        hmma(acc[mt][nt], a0, a1, a2, a3, b0[nt], b1[nt]);
                        hmma(acc[mt][nt], l0, l1, l2, l3, b0[nt], b1[nt]);
                    }
                }
            }

            // ---- store prefetched X into next stage ----
            if (more) {
#pragma unroll
                for (int q = 0; q < 4; q++) {
                    int row = xrow + q * 32;
                    float4 v = px[q];
                    __half hx = __float2half_rn(v.x), hy = __float2half_rn(v.y);
                    __half hz = __float2half_rn(v.z), hw = __float2half_rn(v.w);
                    __half lx = __float2half_rn(v.x - __half2float(hx));
                    __half ly = __float2half_rn(v.y - __half2float(hy));
                    __half lz = __float2half_rn(v.z - __half2float(hz));
                    __half lw = __float2half_rn(v.w - __half2float(hw));
                    uint32_t off = nxt * SZST + row * PXB + xf4 * 8;
                    sts_v2(sb + OFF_XHI + off, pkh(hx, hy), pkh(hz, hw));
                    sts_v2(sb + OFF_XLO + off, pkh(lx, ly), pkh(lz, lw));
                }
                asm volatile("cp.async.wait_group 0;" ::: "memory");
            }
            __syncthreads();
        }

        // ---- epilogue: weights a^(sege-1-t), bias, reduce over rows ----
        const int pbase = sege - 1 - cs;
#pragma unroll
        for (int nt = 0; nt < 4; nt++) {
            const int col = wn * 32 + nt * 8 + lk2;
            const float la0 = l2a_s[col], la1 = l2a_s[col + 1];
            const float bi0 = bias_s[col], bi1 = bias_s[col + 1];
            float s0 = 0.f, s1 = 0.f;
#pragma unroll
            for (int mt = 0; mt < 4; mt++) {
                const int r0 = wm * 64 + mt * 16 + lrow;
                const int p0 = pbase - r0, p1 = p0 - 8;
                if (p0 >= 0) {
                    s0 += exp2f((float)p0 * la0) * (acc[mt][nt][0] + bi0);
                    s1 += exp2f((float)p0 * la1) * (acc[mt][nt][1] + bi1);
                }
                if (p1 >= 0) {
                    s0 += exp2f((float)p1 * la0) * (acc[mt][nt][2] + bi0);
                    s1 += exp2f((float)p1 * la1) * (acc[mt][nt][3] + bi1);
                }
            }
            s0 += __shfl_xor_sync(0xffffffffu, s0, 4);
            s0 += __shfl_xor_sync(0xffffffffu, s0, 8);
            s0 += __shfl_xor_sync(0xffffffffu, s0, 16);
            s1 += __shfl_xor_sync(0xffffffffu, s1, 4);
            s1 += __shfl_xor_sync(0xffffffffu, s1, 8);
            s1 += __shfl_xor_sync(0xffffffffu, s1, 16);
            if (lane < 4) {
                atomicAdd(&acc_s[col], s0);
                atomicAdd(&acc_s[col + 1], s1);
            }
        }
        __syncthreads();
    }

    float* g = stream ? g_Sdec : g_Scorr;
    if (tid < TN_)
        g[(size_t)(b * KS_ + kseg) * H_ + ht0 + tid] = acc_s[tid];
}

// ---------- kernel 2: K-step prefix scan ----------
__global__ void k_scan(const float* __restrict__ araw) {
    int idx = blockIdx.x * blockDim.x + threadIdx.x;
    if (idx >= B_ * H_) return;
    int b = idx / H_, h = idx % H_;
    float a = 1.0f / (1.0f + expf(-araw[h]));
    float l2a = log2f(a);
    float hp = 0.0f;
    for (int k = 0; k < KS_; k++) {
        int len = g_ends[b * KS_ + k] - g_starts[b * KS_ + k];
        float ap = exp2f((float)len * l2a);
        size_t o = (size_t)(b * KS_ + k) * H_ + h;
        g_hT[o] = fmaf(ap, hp, g_Sdec[o]);
        hp      = fmaf(ap, hp, g_Scorr[o]);
    }
}

// ---------- kernel 3: small fp32 GEMM heads ----------
template <bool SILU>
__global__ void k_gemm_small(const float* __restrict__ A, const float* __restrict__ Bm,
                             const float* __restrict__ bias, float* __restrict__ C,
                             int M, int N, int Kd) {
    __shared__ float Asm[32][36];
    __shared__ float Bsm[32][64];
    const int n0 = blockIdx.x * 64, m0 = blockIdx.y * 32;
    const int tid = threadIdx.x;
    const int r0 = (tid >> 5) * 4, c0 = (tid & 31) * 2;
    float acc[4][2];
#pragma unroll
    for (int i = 0; i < 4; i++) { acc[i][0] = 0.f; acc[i][1] = 0.f; }
    const int lam = tid >> 3, lak = (tid & 7) * 4;
    for (int kt = 0; kt < Kd; kt += 32) {
        float4 va = *reinterpret_cast<const float4*>(A + (size_t)(m0 + lam) * Kd + kt + lak);
        Asm[lak + 0][lam] = va.x; Asm[lak + 1][lam] = va.y;
        Asm[lak + 2][lam] = va.z; Asm[lak + 3][lam] = va.w;
#pragma unroll
        for (int q = 0; q < 2; q++) {
            int e = tid + q * 256, kk = e >> 4, c4 = (e & 15) * 4;
            *reinterpret_cast<float4*>(&Bsm[kk][c4]) =
                *reinterpret_cast<const float4*>(Bm + (size_t)(kt + kk) * N + n0 + c4);
        }
        __syncthreads();
#pragma unroll
        for (int kk = 0; kk < 32; kk++) {
            float a0 = Asm[kk][r0], a1 = Asm[kk][r0 + 1], a2 = Asm[kk][r0 + 2], a3 = Asm[kk][r0 + 3];
            float b0 = Bsm[kk][c0], b1 = Bsm[kk][c0 + 1];
            acc[0][0] = fmaf(a0, b0, acc[0][0]); acc[0][1] = fmaf(a0, b1, acc[0][1]);
            acc[1][0] = fmaf(a1, b0, acc[1][0]); acc[1][1] = fmaf(a1, b1, acc[1][1]);
            acc[2][0] = fmaf(a2, b0, acc[2][0]); acc[2][1] = fmaf(a2, b1, acc[2][1]);
            acc[3][0] = fmaf(a3, b0, acc[3][0]); acc[3][1] = fmaf(a3, b1, acc[3][1]);
        }
        __syncthreads();
    }
#pragma unroll
    for (int i = 0; i < 4; i++)
#pragma unroll
        for (int j = 0; j < 2; j++) {
            int row = m0 + r0 + i, col = n0 + c0 + j;
            float v = acc[i][j] + bias[col];
            if (SILU) v = v / (1.0f + expf(-v));
            C[(size_t)row * N + col] = v;
        }
}

// ---------- launcher ----------
extern "C" void kernel_launch(void* const* d_in, const int* in_sizes, int n_in,
                              void* d_out, int out_size) {
    (void)in_sizes; (void)n_in; (void)out_size;
    const float* dec  = (const float*)d_in[0];
    const float* tgt  = (const float*)d_in[1];
    const float* Wp   = (const float*)d_in[2];
    const float* bp   = (const float*)d_in[3];
    const float* araw = (const float*)d_in[4];
    const float* Wout = (const float*)d_in[5];
    const float* bout = (const float*)d_in[6];
    const float* Wmu  = (const float*)d_in[7];
    const float* bmu  = (const float*)d_in[8];
    const float* Wlv  = (const float*)d_in[9];
    const float* blv  = (const float*)d_in[10];
    const int*   mask = (const int*)  d_in[11];
    float* out = (float*)d_out;

    void *pHT = nullptr, *pY = nullptr;
    cudaGetSymbolAddress(&pHT, g_hT);
    cudaGetSymbolAddress(&pY,  g_y);
    cudaFuncSetAttribute(k_mma, cudaFuncAttributeMaxDynamicSharedMemorySize, SMEM_DYN);

    k_bounds<<<B_, 256>>>(mask);
    k_prepW<<<dim3(H_ / 32, D_ / 32), dim3(32, 8)>>>(Wp);
    dim3 g1(H_ / TN_, KS_, B_ * 2);
    k_mma<<<g1, 256, SMEM_DYN>>>(tgt, dec, bp, araw);
    k_scan<<<(B_ * H_) / 256, 256>>>(araw);
    k_gemm_small<true ><<<dim3(H_ / 64,  (B_ * KS_) / 32), 256>>>(
        (const float*)pHT, Wout, bout, (float*)pY, B_ * KS_, H_, H_);
    k_gemm_small<false><<<dim3(LAT_ / 64, (B_ * KS_) / 32), 256>>>(
        (const float*)pY, Wmu, bmu, out, B_ * KS_, LAT_, H_);
    k_gemm_small<false><<<dim3(LAT_ / 64, (B_ * KS_) / 32), 256>>>(
        (const float*)pY, Wlv, blv, out + (size_t)B_ * KS_ * LAT_, B_ * KS_, LAT_, H_);
}

// round 5
// speedup vs baseline: 5.3288x; 1.6199x over previous
#include <cuda_runtime.h>
#include <cuda_fp16.h>
#include <math.h>
#include <stdint.h>

#define B_   8
#define L_   4096
#define D_   1024
#define H_   1024
#define LAT_ 256
#define KS_  32
#define TM_  128
#define TN_  128
#define BK_  32
#define NCH  (D_ / BK_)   // 32 chunks

#define PXB  80           // smem pitch bytes (32 halves + 8 pad)
#define SZST 10240        // 128 rows * 80 B
#define OFF_XHI 0
#define OFF_W   20480
#define OFF_L2A 40960
#define OFF_BIA 41472
#define OFF_ACC 41984
#define SMEM_DYN 42496

__device__ float g_Scorr[B_ * KS_ * H_];
__device__ float g_Sdec [B_ * KS_ * H_];
__device__ float g_hT   [B_ * KS_ * H_];
__device__ float g_y    [B_ * KS_ * H_];
__device__ int   g_starts[B_ * KS_];
__device__ int   g_ends  [B_ * KS_];
__device__ __half g_Wf16[H_ * D_];      // W^T as fp16: [n][k]

// ---------- helpers ----------
__device__ __forceinline__ uint32_t smem_u32(const void* p) {
    uint32_t a;
    asm("{ .reg .u64 t; cvta.to.shared.u64 t, %1; cvt.u32.u64 %0, t; }" : "=r"(a) : "l"(p));
    return a;
}
__device__ __forceinline__ void sts_v2(uint32_t a, uint32_t x, uint32_t y) {
    asm volatile("st.shared.v2.b32 [%0], {%1,%2};" :: "r"(a), "r"(x), "r"(y));
}
__device__ __forceinline__ void cpa16(uint32_t s, const void* g) {
    unsigned long long gg = (unsigned long long)__cvta_generic_to_global(g);
    asm volatile("cp.async.cg.shared.global [%0], [%1], 16;" :: "r"(s), "l"(gg));
}
__device__ __forceinline__ void ldsm4(uint32_t& r0, uint32_t& r1, uint32_t& r2,
                                      uint32_t& r3, uint32_t a) {
    asm volatile("ldmatrix.sync.aligned.m8n8.x4.shared.b16 {%0,%1,%2,%3}, [%4];"
                 : "=r"(r0), "=r"(r1), "=r"(r2), "=r"(r3) : "r"(a));
}
__device__ __forceinline__ void hmma(float* c, uint32_t a0, uint32_t a1, uint32_t a2,
                                     uint32_t a3, uint32_t b0, uint32_t b1) {
    asm volatile(
        "mma.sync.aligned.m16n8k16.row.col.f32.f16.f16.f32 "
        "{%0,%1,%2,%3}, {%4,%5,%6,%7}, {%8,%9}, {%0,%1,%2,%3};"
        : "+f"(c[0]), "+f"(c[1]), "+f"(c[2]), "+f"(c[3])
        : "r"(a0), "r"(a1), "r"(a2), "r"(a3), "r"(b0), "r"(b1));
}
__device__ __forceinline__ uint32_t pkh(__half a, __half b) {
    return (uint32_t)__half_as_ushort(a) | ((uint32_t)__half_as_ushort(b) << 16);
}

// ---------- kernel 0: segment bounds ----------
__global__ void k_bounds(const int* __restrict__ mask) {
    int b = blockIdx.x, tid = threadIdx.x;
    const int CH = L_ / 256;
    __shared__ int cnt[256], base[256];
    const int* m = mask + (size_t)b * L_ + tid * CH;
    int c = 0;
#pragma unroll
    for (int i = 0; i < CH; i++) c += (m[i] != 0);
    cnt[tid] = c;
    __syncthreads();
    if (tid == 0) { int s = 0; for (int i = 0; i < 256; i++) { base[i] = s; s += cnt[i]; } }
    __syncthreads();
    int r = base[tid];
#pragma unroll
    for (int i = 0; i < CH; i++)
        if (m[i] != 0) { if (r < KS_) g_ends[b * KS_ + r] = tid * CH + i + 1; r++; }
    __syncthreads();
    if (tid < KS_) g_starts[b * KS_ + tid] = (tid == 0) ? 0 : g_ends[b * KS_ + tid - 1];
}

// ---------- kernel 0b: W transpose + fp16 ----------
__global__ void k_prepW(const float* __restrict__ W) {     // W[k][n] -> g_Wf16[n][k]
    __shared__ float t[32][33];
    int n0 = blockIdx.x * 32, k0 = blockIdx.y * 32;
    for (int i = threadIdx.y; i < 32; i += 8)
        t[i][threadIdx.x] = W[(size_t)(k0 + i) * H_ + n0 + threadIdx.x];
    __syncthreads();
    for (int i = threadIdx.y; i < 32; i += 8)
        g_Wf16[(size_t)(n0 + i) * D_ + (k0 + threadIdx.x)] = __float2half_rn(t[threadIdx.x][i]);
}

// ---------- kernel 1: HMMA fused GEMM + weighted segment reduce ----------
__global__ __launch_bounds__(256, 2)
void k_mma(const float* __restrict__ Xtgt, const float* __restrict__ Xdec,
           const float* __restrict__ bproj, const float* __restrict__ araw) {
    extern __shared__ char smem[];
    const uint32_t sb = smem_u32(smem);

    const int tid = threadIdx.x, wid = tid >> 5, lane = tid & 31;
    const int wm = wid >> 2, wn = wid & 3;              // warp grid 2(M) x 4(N)
    const int z = blockIdx.z, b = z >> 1, stream = z & 1;
    const int kseg = blockIdx.y, ht0 = blockIdx.x * TN_;
    const float* __restrict__ Xb = (stream ? Xdec : Xtgt) + (size_t)b * L_ * D_;
    const int segs = g_starts[b * KS_ + kseg];
    const int sege = g_ends  [b * KS_ + kseg];

    float* l2a_s  = (float*)(smem + OFF_L2A);
    float* bias_s = (float*)(smem + OFF_BIA);
    float* acc_s  = (float*)(smem + OFF_ACC);
    if (tid < TN_) {
        float a = 1.0f / (1.0f + expf(-araw[ht0 + tid]));
        l2a_s[tid]  = log2f(a);
        bias_s[tid] = bproj[ht0 + tid];
        acc_s[tid]  = 0.0f;
    }
    __syncthreads();

    // loader indices
    const int xrow = tid >> 3, xf4 = tid & 7;           // X: 8 float4 per row
    // fragment (ldmatrix) per-lane offsets
    const int lane7 = lane & 7;
    const uint32_t a_off = (uint32_t)((wm * 64 + ((lane >> 3) & 1) * 8 + lane7) * PXB
                                      + ((lane >> 4) & 1) * 16);
    const uint32_t b_off = (uint32_t)((wn * 32 + ((lane >> 4) & 1) * 8 + lane7) * PXB
                                      + ((lane >> 3) & 1) * 16);
    // epilogue lane mapping (C fragment)
    const int lrow = lane >> 2, lk2 = (lane & 3) * 2;

    for (int cs = segs; cs < sege; cs += TM_) {
        float acc[4][4][4];
#pragma unroll
        for (int i = 0; i < 4; i++)
#pragma unroll
            for (int j = 0; j < 4; j++)
#pragma unroll
                for (int q = 0; q < 4; q++) acc[i][j][q] = 0.0f;

        // ---- load chunk 0 into stage 0 ----
        {
#pragma unroll
            for (int q = 0; q < 4; q++) {
                int row = xrow + q * 32;
                int t = cs + row;
                float4 v = make_float4(0.f, 0.f, 0.f, 0.f);
                if (t < sege) v = *(const float4*)(Xb + (size_t)t * D_ + xf4 * 4);
                sts_v2(sb + OFF_XHI + row * PXB + xf4 * 8,
                       pkh(__float2half_rn(v.x), __float2half_rn(v.y)),
                       pkh(__float2half_rn(v.z), __float2half_rn(v.w)));
            }
#pragma unroll
            for (int q = 0; q < 2; q++) {
                int idx = tid + q * 256;
                int row = idx >> 2, sg = idx & 3;
                cpa16(sb + OFF_W + row * PXB + sg * 16,
                      g_Wf16 + (size_t)(ht0 + row) * D_ + sg * 8);
            }
            asm volatile("cp.async.commit_group;");
            asm volatile("cp.async.wait_group 0;" ::: "memory");
            __syncthreads();
        }

#pragma unroll 1
        for (int c = 0; c < NCH; c++) {
            const int cur = c & 1, nxt = cur ^ 1;
            const bool more = (c + 1 < NCH);

            // prefetch next chunk: X -> regs, W -> cp.async
            float4 px[4];
            if (more) {
                const int kt = (c + 1) * BK_;
#pragma unroll
                for (int q = 0; q < 4; q++) {
                    int row = xrow + q * 32;
                    int t = cs + row;
                    px[q] = make_float4(0.f, 0.f, 0.f, 0.f);
                    if (t < sege) px[q] = *(const float4*)(Xb + (size_t)t * D_ + kt + xf4 * 4);
                }
#pragma unroll
                for (int q = 0; q < 2; q++) {
                    int idx = tid + q * 256;
                    int row = idx >> 2, sg = idx & 3;
                    cpa16(sb + OFF_W + nxt * SZST + row * PXB + sg * 16,
                          g_Wf16 + (size_t)(ht0 + row) * D_ + kt + sg * 8);
                }
                asm volatile("cp.async.commit_group;");
            }

            // ---- compute current chunk (2 k16 steps), ldmatrix fragments ----
            const uint32_t xh = sb + OFF_XHI + cur * SZST;
            const uint32_t wb = sb + OFF_W   + cur * SZST;
#pragma unroll
            for (int ks = 0; ks < 2; ks++) {
                uint32_t b0[4], b1[4];
#pragma unroll
                for (int p = 0; p < 2; p++)
                    ldsm4(b0[2 * p], b1[2 * p], b0[2 * p + 1], b1[2 * p + 1],
                          wb + b_off + p * (16 * PXB) + ks * 32);
#pragma unroll
                for (int mt = 0; mt < 4; mt++) {
                    uint32_t a0, a1, a2, a3;
                    ldsm4(a0, a1, a2, a3, xh + a_off + mt * (16 * PXB) + ks * 32);
#pragma unroll
                    for (int nt = 0; nt < 4; nt++)
                        hmma(acc[mt][nt], a0, a1, a2, a3, b0[nt], b1[nt]);
                }
            }

            // ---- store prefetched X into next stage ----
            if (more) {
#pragma unroll
                for (int q = 0; q < 4; q++) {
                    int row = xrow + q * 32;
                    float4 v = px[q];
                    sts_v2(sb + OFF_XHI + nxt * SZST + row * PXB + xf4 * 8,
                           pkh(__float2half_rn(v.x), __float2half_rn(v.y)),
                           pkh(__float2half_rn(v.z), __float2half_rn(v.w)));
                }
                asm volatile("cp.async.wait_group 0;" ::: "memory");
            }
            __syncthreads();
        }

        // ---- epilogue: weights a^(sege-1-t), bias, reduce over rows ----
        const int pbase = sege - 1 - cs;
#pragma unroll
        for (int nt = 0; nt < 4; nt++) {
            const int col = wn * 32 + nt * 8 + lk2;
            const float la0 = l2a_s[col], la1 = l2a_s[col + 1];
            const float bi0 = bias_s[col], bi1 = bias_s[col + 1];
            float s0 = 0.f, s1 = 0.f;
#pragma unroll
            for (int mt = 0; mt < 4; mt++) {
                const int r0 = wm * 64 + mt * 16 + lrow;
                const int p0 = pbase - r0, p1 = p0 - 8;
                if (p0 >= 0) {
                    s0 += exp2f((float)p0 * la0) * (acc[mt][nt][0] + bi0);
                    s1 += exp2f((float)p0 * la1) * (acc[mt][nt][1] + bi1);
                }
                if (p1 >= 0) {
                    s0 += exp2f((float)p1 * la0) * (acc[mt][nt][2] + bi0);
                    s1 += exp2f((float)p1 * la1) * (acc[mt][nt][3] + bi1);
                }
            }
            s0 += __shfl_xor_sync(0xffffffffu, s0, 4);
            s0 += __shfl_xor_sync(0xffffffffu, s0, 8);
            s0 += __shfl_xor_sync(0xffffffffu, s0, 16);
            s1 += __shfl_xor_sync(0xffffffffu, s1, 4);
            s1 += __shfl_xor_sync(0xffffffffu, s1, 8);
            s1 += __shfl_xor_sync(0xffffffffu, s1, 16);
            if (lane < 4) {
                atomicAdd(&acc_s[col], s0);
                atomicAdd(&acc_s[col + 1], s1);
            }
        }
        __syncthreads();
    }

    float* g = stream ? g_Sdec : g_Scorr;
    if (tid < TN_)
        g[(size_t)(b * KS_ + kseg) * H_ + ht0 + tid] = acc_s[tid];
}

// ---------- kernel 2: K-step prefix scan ----------
__global__ void k_scan(const float* __restrict__ araw) {
    int idx = blockIdx.x * blockDim.x + threadIdx.x;
    if (idx >= B_ * H_) return;
    int b = idx / H_, h = idx % H_;
    float a = 1.0f / (1.0f + expf(-araw[h]));
    float l2a = log2f(a);
    float hp = 0.0f;
    for (int k = 0; k < KS_; k++) {
        int len = g_ends[b * KS_ + k] - g_starts[b * KS_ + k];
        float ap = exp2f((float)len * l2a);
        size_t o = (size_t)(b * KS_ + k) * H_ + h;
        g_hT[o] = fmaf(ap, hp, g_Sdec[o]);
        hp      = fmaf(ap, hp, g_Scorr[o]);
    }
}

// ---------- heads: bias fill / split-K GEMM (atomic) / SiLU ----------
__global__ void k_fill_bias(float* __restrict__ C, const float* __restrict__ bias,
                            int N4, int total4) {
    int i = blockIdx.x * blockDim.x + threadIdx.x;
    if (i >= total4) return;
    ((float4*)C)[i] = ((const float4*)bias)[i % N4];
}

__global__ void k_silu(float* __restrict__ y, int n) {
    int i = blockIdx.x * blockDim.x + threadIdx.x;
    if (i >= n) return;
    float v = y[i];
    y[i] = v / (1.0f + expf(-v));
}

__global__ void k_gemm_splitk(const float* __restrict__ A, const float* __restrict__ Bm,
                              float* __restrict__ C, int M, int N, int Kd, int ksplit) {
    __shared__ float Asm[32][36];
    __shared__ float Bsm[32][64];
    const int n0 = blockIdx.x * 64, m0 = blockIdx.y * 32;
    const int kchunk = Kd / ksplit;
    const int kbeg = blockIdx.z * kchunk, kend = kbeg + kchunk;
    const int tid = threadIdx.x;
    const int r0 = (tid >> 5) * 4, c0 = (tid & 31) * 2;
    float acc[4][2];
#pragma unroll
    for (int i = 0; i < 4; i++) { acc[i][0] = 0.f; acc[i][1] = 0.f; }
    const int lam = tid >> 3, lak = (tid & 7) * 4;
    for (int kt = kbeg; kt < kend; kt += 32) {
        float4 va = *reinterpret_cast<const float4*>(A + (size_t)(m0 + lam) * Kd + kt + lak);
        Asm[lak + 0][lam] = va.x; Asm[lak + 1][lam] = va.y;
        Asm[lak + 2][lam] = va.z; Asm[lak + 3][lam] = va.w;
#pragma unroll
        for (int q = 0; q < 2; q++) {
            int e = tid + q * 256, kk = e >> 4, c4 = (e & 15) * 4;
            *reinterpret_cast<float4*>(&Bsm[kk][c4]) =
                *reinterpret_cast<const float4*>(Bm + (size_t)(kt + kk) * N + n0 + c4);
        }
        __syncthreads();
#pragma unroll
        for (int kk = 0; kk < 32; kk++) {
            float a0 = Asm[kk][r0], a1 = Asm[kk][r0 + 1], a2 = Asm[kk][r0 + 2], a3 = Asm[kk][r0 + 3];
            float b0 = Bsm[kk][c0], b1 = Bsm[kk][c0 + 1];
            acc[0][0] = fmaf(a0, b0, acc[0][0]); acc[0][1] = fmaf(a0, b1, acc[0][1]);
            acc[1][0] = fmaf(a1, b0, acc[1][0]); acc[1][1] = fmaf(a1, b1, acc[1][1]);
            acc[2][0] = fmaf(a2, b0, acc[2][0]); acc[2][1] = fmaf(a2, b1, acc[2][1]);
            acc[3][0] = fmaf(a3, b0, acc[3][0]); acc[3][1] = fmaf(a3, b1, acc[3][1]);
        }
        __syncthreads();
    }
#pragma unroll
    for (int i = 0; i < 4; i++)
#pragma unroll
        for (int j = 0; j < 2; j++)
            atomicAdd(&C[(size_t)(m0 + r0 + i) * N + n0 + c0 + j], acc[i][j]);
}

// ---------- launcher ----------
extern "C" void kernel_launch(void* const* d_in, const int* in_sizes, int n_in,
                              void* d_out, int out_size) {
    (void)in_sizes; (void)n_in; (void)out_size;
    const float* dec  = (const float*)d_in[0];
    const float* tgt  = (const float*)d_in[1];
    const float* Wp   = (const float*)d_in[2];
    const float* bp   = (const float*)d_in[3];
    const float* araw = (const float*)d_in[4];
    const float* Wout = (const float*)d_in[5];
    const float* bout = (const float*)d_in[6];
    const float* Wmu  = (const float*)d_in[7];
    const float* bmu  = (const float*)d_in[8];
    const float* Wlv  = (const float*)d_in[9];
    const float* blv  = (const float*)d_in[10];
    const int*   mask = (const int*)  d_in[11];
    float* out = (float*)d_out;

    void *pHT = nullptr, *pY = nullptr;
    cudaGetSymbolAddress(&pHT, g_hT);
    cudaGetSymbolAddress(&pY,  g_y);
    float* dY  = (float*)pY;
    float* dHT = (float*)pHT;
    cudaFuncSetAttribute(k_mma, cudaFuncAttributeMaxDynamicSharedMemorySize, SMEM_DYN);

    const int M = B_ * KS_;   // 256

    k_bounds<<<B_, 256>>>(mask);
    k_prepW<<<dim3(H_ / 32, D_ / 32), dim3(32, 8)>>>(Wp);
    dim3 g1(H_ / TN_, KS_, B_ * 2);
    k_mma<<<g1, 256, SMEM_DYN>>>(tgt, dec, bp, araw);
    k_scan<<<(B_ * H_) / 256, 256>>>(araw);

    // y = silu(hT @ W_out + b_out), split-K
    k_fill_bias<<<(M * H_ / 4 + 255) / 256, 256>>>(dY, bout, H_ / 4, M * H_ / 4);
    k_gemm_splitk<<<dim3(H_ / 64, M / 32, 4), 256>>>(dHT, Wout, dY, M, H_, H_, 4);
    k_silu<<<(M * H_ + 255) / 256, 256>>>(dY, M * H_);

    // mu / logvar heads, split-K
    float* outMu = out;
    float* outLv = out + (size_t)M * LAT_;
    k_fill_bias<<<(M * LAT_ / 4 + 255) / 256, 256>>>(outMu, bmu, LAT_ / 4, M * LAT_ / 4);
    k_fill_bias<<<(M * LAT_ / 4 + 255) / 256, 256>>>(outLv, blv, LAT_ / 4, M * LAT_ / 4);
    k_gemm_splitk<<<dim3(LAT_ / 64, M / 32, 4), 256>>>(dY, Wmu, outMu, M, LAT_, H_, 4);
    k_gemm_splitk<<<dim3(LAT_ / 64, M / 32, 4), 256>>>(dY, Wlv, outLv, M, LAT_, H_, 4);
}

// round 7
// speedup vs baseline: 5.6119x; 1.0531x over previous
#include <cuda_runtime.h>
#include <cuda_fp16.h>
#include <math.h>
#include <stdint.h>

#define B_   8
#define L_   4096
#define D_   1024
#define H_   1024
#define LAT_ 256
#define KS_  32
#define TM_  128
#define TN_  128
#define BK_  32
#define NCH  (D_ / BK_)   // 32 chunks

#define PXB  80           // smem pitch bytes (32 halves + 8 pad)
#define SZST 10240        // 128 rows * 80 B per stage
#define NSTG 3
#define OFF_X   0
#define OFF_W   (NSTG * SZST)            // 30720
#define OFF_L2A (2 * NSTG * SZST)        // 61440
#define OFF_BIA (OFF_L2A + 512)
#define OFF_ACC (OFF_L2A + 1024)
#define SMEM_DYN (OFF_L2A + 1536)

__device__ float g_Scorr[B_ * KS_ * H_];
__device__ float g_Sdec [B_ * KS_ * H_];
__device__ float g_hT   [B_ * KS_ * H_];
__device__ float g_y    [B_ * KS_ * H_];
__device__ int   g_starts[B_ * KS_];
__device__ int   g_ends  [B_ * KS_];
__device__ __half g_Wf16[H_ * D_];           // W^T fp16 [n][k]
__device__ __half g_X16[2 * B_ * L_ * D_];   // [stream][b][t][d] fp16

// ---------- helpers ----------
__device__ __forceinline__ uint32_t smem_u32(const void* p) {
    uint32_t a;
    asm("{ .reg .u64 t; cvta.to.shared.u64 t, %1; cvt.u32.u64 %0, t; }" : "=r"(a) : "l"(p));
    return a;
}
__device__ __forceinline__ void cpa16(uint32_t s, const void* g) {
    unsigned long long gg = (unsigned long long)__cvta_generic_to_global(g);
    asm volatile("cp.async.cg.shared.global [%0], [%1], 16;" :: "r"(s), "l"(gg));
}
__device__ __forceinline__ void ldsm4(uint32_t& r0, uint32_t& r1, uint32_t& r2,
                                      uint32_t& r3, uint32_t a) {
    asm volatile("ldmatrix.sync.aligned.m8n8.x4.shared.b16 {%0,%1,%2,%3}, [%4];"
                 : "=r"(r0), "=r"(r1), "=r"(r2), "=r"(r3) : "r"(a));
}
__device__ __forceinline__ void hmma(float* c, uint32_t a0, uint32_t a1, uint32_t a2,
                                     uint32_t a3, uint32_t b0, uint32_t b1) {
    asm volatile(
        "mma.sync.aligned.m16n8k16.row.col.f32.f16.f16.f32 "
        "{%0,%1,%2,%3}, {%4,%5,%6,%7}, {%8,%9}, {%0,%1,%2,%3};"
        : "+f"(c[0]), "+f"(c[1]), "+f"(c[2]), "+f"(c[3])
        : "r"(a0), "r"(a1), "r"(a2), "r"(a3), "r"(b0), "r"(b1));
}

// ---------- kernel 0: segment bounds ----------
__global__ void k_bounds(const int* __restrict__ mask) {
    int b = blockIdx.x, tid = threadIdx.x;
    const int CH = L_ / 256;
    __shared__ int cnt[256], base[256];
    const int* m = mask + (size_t)b * L_ + tid * CH;
    int c = 0;
#pragma unroll
    for (int i = 0; i < CH; i++) c += (m[i] != 0);
    cnt[tid] = c;
    __syncthreads();
    if (tid == 0) { int s = 0; for (int i = 0; i < 256; i++) { base[i] = s; s += cnt[i]; } }
    __syncthreads();
    int r = base[tid];
#pragma unroll
    for (int i = 0; i < CH; i++)
        if (m[i] != 0) { if (r < KS_) g_ends[b * KS_ + r] = tid * CH + i + 1; r++; }
    __syncthreads();
    if (tid < KS_) g_starts[b * KS_ + tid] = (tid == 0) ? 0 : g_ends[b * KS_ + tid - 1];
}

// ---------- kernel 0b: W transpose + fp16 ----------
__global__ void k_prepW(const float* __restrict__ W) {     // W[k][n] -> g_Wf16[n][k]
    __shared__ float t[32][33];
    int n0 = blockIdx.x * 32, k0 = blockIdx.y * 32;
    for (int i = threadIdx.y; i < 32; i += 8)
        t[i][threadIdx.x] = W[(size_t)(k0 + i) * H_ + n0 + threadIdx.x];
    __syncthreads();
    for (int i = threadIdx.y; i < 32; i += 8)
        g_Wf16[(size_t)(n0 + i) * D_ + (k0 + threadIdx.x)] = __float2half_rn(t[threadIdx.x][i]);
}

// ---------- kernel 0c: X -> fp16 ----------
__global__ void k_prepX(const float* __restrict__ src, __half* __restrict__ dst) {
    size_t i = (size_t)(blockIdx.x * blockDim.x + threadIdx.x) * 8;
    float4 v0 = *(const float4*)(src + i);
    float4 v1 = *(const float4*)(src + i + 4);
    __half2 h[4];
    h[0] = __floats2half2_rn(v0.x, v0.y);
    h[1] = __floats2half2_rn(v0.z, v0.w);
    h[2] = __floats2half2_rn(v1.x, v1.y);
    h[3] = __floats2half2_rn(v1.z, v1.w);
    *(uint4*)(dst + i) = *(uint4*)h;
}

// ---------- kernel 1: HMMA fused GEMM + weighted segment reduce ----------
__global__ __launch_bounds__(256, 2)
void k_mma(const float* __restrict__ bproj, const float* __restrict__ araw) {
    extern __shared__ char smem[];
    const uint32_t sb = smem_u32(smem);

    const int tid = threadIdx.x, wid = tid >> 5, lane = tid & 31;
    const int wm = wid >> 2, wn = wid & 3;
    const int z = blockIdx.z, b = z >> 1, stream = z & 1;
    const int kseg = blockIdx.y, ht0 = blockIdx.x * TN_;
    const __half* __restrict__ Xb =
        g_X16 + ((size_t)stream * B_ + b) * L_ * D_;
    const int segs = g_starts[b * KS_ + kseg];
    const int sege = g_ends  [b * KS_ + kseg];

    float* l2a_s  = (float*)(smem + OFF_L2A);
    float* bias_s = (float*)(smem + OFF_BIA);
    float* acc_s  = (float*)(smem + OFF_ACC);
    if (tid < TN_) {
        float a = 1.0f / (1.0f + expf(-araw[ht0 + tid]));
        l2a_s[tid]  = log2f(a);
        bias_s[tid] = bproj[ht0 + tid];
        acc_s[tid]  = 0.0f;
    }

    // loader: row = tid>>2 (0..63) and row+64; 4 threads x 16B per row
    const int lrw = tid >> 2, lsg = (tid & 3) * 16;
    // ldmatrix per-lane offsets
    const int lane7 = lane & 7;
    const uint32_t a_off = (uint32_t)((wm * 64 + ((lane >> 3) & 1) * 8 + lane7) * PXB
                                      + ((lane >> 4) & 1) * 16);
    const uint32_t b_off = (uint32_t)((wn * 32 + ((lane >> 4) & 1) * 8 + lane7) * PXB
                                      + ((lane >> 3) & 1) * 16);
    const int lrow = lane >> 2, lk2 = (lane & 3) * 2;

    for (int cs = segs; cs < sege; cs += TM_) {
        float acc[4][4][4];
#pragma unroll
        for (int i = 0; i < 4; i++)
#pragma unroll
            for (int j = 0; j < 4; j++)
#pragma unroll
                for (int q = 0; q < 4; q++) acc[i][j][q] = 0.0f;

        // rows clamped to valid memory; epilogue drops p<0 rows
        const int xr0 = (cs + lrw      < L_) ? (cs + lrw)      : (L_ - 1);
        const int xr1 = (cs + lrw + 64 < L_) ? (cs + lrw + 64) : (L_ - 1);

        // prologue: stages 0..2
#pragma unroll
        for (int s = 0; s < NSTG; s++) {
            const int kt = s * BK_;
            cpa16(sb + OFF_X + s * SZST + lrw * PXB + lsg,
                  Xb + (size_t)xr0 * D_ + kt + lsg / 2);
            cpa16(sb + OFF_X + s * SZST + (lrw + 64) * PXB + lsg,
                  Xb + (size_t)xr1 * D_ + kt + lsg / 2);
            cpa16(sb + OFF_W + s * SZST + lrw * PXB + lsg,
                  g_Wf16 + (size_t)(ht0 + lrw) * D_ + kt + lsg / 2);
            cpa16(sb + OFF_W + s * SZST + (lrw + 64) * PXB + lsg,
                  g_Wf16 + (size_t)(ht0 + lrw + 64) * D_ + kt + lsg / 2);
            asm volatile("cp.async.commit_group;");
        }

#pragma unroll 1
        for (int c = 0; c < NCH; c++) {
            const int cur = c % NSTG;
            if (c < NCH - 2)       asm volatile("cp.async.wait_group 2;" ::: "memory");
            else if (c == NCH - 2) asm volatile("cp.async.wait_group 1;" ::: "memory");
            else                   asm volatile("cp.async.wait_group 0;" ::: "memory");
            __syncthreads();

            const uint32_t xh = sb + OFF_X + cur * SZST;
            const uint32_t wb = sb + OFF_W + cur * SZST;
#pragma unroll
            for (int ks = 0; ks < 2; ks++) {
                uint32_t b0[4], b1[4];
#pragma unroll
                for (int p = 0; p < 2; p++)
                    ldsm4(b0[2 * p], b1[2 * p], b0[2 * p + 1], b1[2 * p + 1],
                          wb + b_off + p * (16 * PXB) + ks * 32);
#pragma unroll
                for (int mt = 0; mt < 4; mt++) {
                    uint32_t a0, a1, a2, a3;
                    ldsm4(a0, a1, a2, a3, xh + a_off + mt * (16 * PXB) + ks * 32);
#pragma unroll
                    for (int nt = 0; nt < 4; nt++)
                        hmma(acc[mt][nt], a0, a1, a2, a3, b0[nt], b1[nt]);
                }
            }
            __syncthreads();

            if (c + NSTG < NCH) {
                const int kt = (c + NSTG) * BK_;
                const uint32_t st = sb + (uint32_t)(((c + NSTG) % NSTG) * SZST);
                cpa16(st + OFF_X + lrw * PXB + lsg, Xb + (size_t)xr0 * D_ + kt + lsg / 2);
                cpa16(st + OFF_X + (lrw + 64) * PXB + lsg, Xb + (size_t)xr1 * D_ + kt + lsg / 2);
                cpa16(st + OFF_W + lrw * PXB + lsg,
                      g_Wf16 + (size_t)(ht0 + lrw) * D_ + kt + lsg / 2);
                cpa16(st + OFF_W + (lrw + 64) * PXB + lsg,
                      g_Wf16 + (size_t)(ht0 + lrw + 64) * D_ + kt + lsg / 2);
                asm volatile("cp.async.commit_group;");
            }
        }

        // ---- epilogue ----
        const int pbase = sege - 1 - cs;
#pragma unroll
        for (int nt = 0; nt < 4; nt++) {
            const int col = wn * 32 + nt * 8 + lk2;
            const float la0 = l2a_s[col], la1 = l2a_s[col + 1];
            const float bi0 = bias_s[col], bi1 = bias_s[col + 1];
            float s0 = 0.f, s1 = 0.f;
#pragma unroll
            for (int mt = 0; mt < 4; mt++) {
                const int r0 = wm * 64 + mt * 16 + lrow;
                const int p0 = pbase - r0, p1 = p0 - 8;
                if (p0 >= 0) {
                    s0 += exp2f((float)p0 * la0) * (acc[mt][nt][0] + bi0);
                    s1 += exp2f((float)p0 * la1) * (acc[mt][nt][1] + bi1);
                }
                if (p1 >= 0) {
                    s0 += exp2f((float)p1 * la0) * (acc[mt][nt][2] + bi0);
                    s1 += exp2f((float)p1 * la1) * (acc[mt][nt][3] + bi1);
                }
            }
            s0 += __shfl_xor_sync(0xffffffffu, s0, 4);
            s0 += __shfl_xor_sync(0xffffffffu, s0, 8);
            s0 += __shfl_xor_sync(0xffffffffu, s0, 16);
            s1 += __shfl_xor_sync(0xffffffffu, s1, 4);
            s1 += __shfl_xor_sync(0xffffffffu, s1, 8);
            s1 += __shfl_xor_sync(0xffffffffu, s1, 16);
            if (lane < 4) {
                atomicAdd(&acc_s[col], s0);
                atomicAdd(&acc_s[col + 1], s1);
            }
        }
        __syncthreads();
    }

    float* g = stream ? g_Sdec : g_Scorr;
    if (tid < TN_)
        g[(size_t)(b * KS_ + kseg) * H_ + ht0 + tid] = acc_s[tid];
}

// ---------- kernel 2: K-step prefix scan ----------
__global__ void k_scan(const float* __restrict__ araw) {
    int idx = blockIdx.x * blockDim.x + threadIdx.x;
    if (idx >= B_ * H_) return;
    int b = idx / H_, h = idx % H_;
    float a = 1.0f / (1.0f + expf(-araw[h]));
    float l2a = log2f(a);
    float hp = 0.0f;
    for (int k = 0; k < KS_; k++) {
        int len = g_ends[b * KS_ + k] - g_starts[b * KS_ + k];
        float ap = exp2f((float)len * l2a);
        size_t o = (size_t)(b * KS_ + k) * H_ + h;
        g_hT[o] = fmaf(ap, hp, g_Sdec[o]);
        hp      = fmaf(ap, hp, g_Scorr[o]);
    }
}

// ---------- heads ----------
__global__ void k_fill_bias(float* __restrict__ C, const float* __restrict__ bias,
                            int N4, int total4) {
    int i = blockIdx.x * blockDim.x + threadIdx.x;
    if (i >= total4) return;
    ((float4*)C)[i] = ((const float4*)bias)[i % N4];
}

__global__ void k_silu(float* __restrict__ y, int n) {
    int i = blockIdx.x * blockDim.x + threadIdx.x;
    if (i >= n) return;
    float v = y[i];
    y[i] = v / (1.0f + expf(-v));
}

__global__ void k_gemm_splitk(const float* __restrict__ A, const float* __restrict__ Bm,
                              float* __restrict__ C, int M, int N, int Kd, int ksplit) {
    __shared__ float Asm[32][36];
    __shared__ float Bsm[32][64];
    const int n0 = blockIdx.x * 64, m0 = blockIdx.y * 32;
    const int kchunk = Kd / ksplit;
    const int kbeg = blockIdx.z * kchunk, kend = kbeg + kchunk;
    const int tid = threadIdx.x;
    const int r0 = (tid >> 5) * 4, c0 = (tid & 31) * 2;
    float acc[4][2];
#pragma unroll
    for (int i = 0; i < 4; i++) { acc[i][0] = 0.f; acc[i][1] = 0.f; }
    const int lam = tid >> 3, lak = (tid & 7) * 4;
    for (int kt = kbeg; kt < kend; kt += 32) {
        float4 va = *reinterpret_cast<const float4*>(A + (size_t)(m0 + lam) * Kd + kt + lak);
        Asm[lak + 0][lam] = va.x; Asm[lak + 1][lam] = va.y;
        Asm[lak + 2][lam] = va.z; Asm[lak + 3][lam] = va.w;
#pragma unroll
        for (int q = 0; q < 2; q++) {
            int e = tid + q * 256, kk = e >> 4, c4 = (e & 15) * 4;
            *reinterpret_cast<float4*>(&Bsm[kk][c4]) =
                *reinterpret_cast<const float4*>(Bm + (size_t)(kt + kk) * N + n0 + c4);
        }
        __syncthreads();
#pragma unroll
        for (int kk = 0; kk < 32; kk++) {
            float a0 = Asm[kk][r0], a1 = Asm[kk][r0 + 1], a2 = Asm[kk][r0 + 2], a3 = Asm[kk][r0 + 3];
            float b0 = Bsm[kk][c0], b1 = Bsm[kk][c0 + 1];
            acc[0][0] = fmaf(a0, b0, acc[0][0]); acc[0][1] = fmaf(a0, b1, acc[0][1]);
            acc[1][0] = fmaf(a1, b0, acc[1][0]); acc[1][1] = fmaf(a1, b1, acc[1][1]);
            acc[2][0] = fmaf(a2, b0, acc[2][0]); acc[2][1] = fmaf(a2, b1, acc[2][1]);
            acc[3][0] = fmaf(a3, b0, acc[3][0]); acc[3][1] = fmaf(a3, b1, acc[3][1]);
        }
        __syncthreads();
    }
#pragma unroll
    for (int i = 0; i < 4; i++)
#pragma unroll
        for (int j = 0; j < 2; j++)
            atomicAdd(&C[(size_t)(m0 + r0 + i) * N + n0 + c0 + j], acc[i][j]);
}

// ---------- launcher ----------
extern "C" void kernel_launch(void* const* d_in, const int* in_sizes, int n_in,
                              void* d_out, int out_size) {
    (void)in_sizes; (void)n_in; (void)out_size;
    const float* dec  = (const float*)d_in[0];
    const float* tgt  = (const float*)d_in[1];
    const float* Wp   = (const float*)d_in[2];
    const float* bp   = (const float*)d_in[3];
    const float* araw = (const float*)d_in[4];
    const float* Wout = (const float*)d_in[5];
    const float* bout = (const float*)d_in[6];
    const float* Wmu  = (const float*)d_in[7];
    const float* bmu  = (const float*)d_in[8];
    const float* Wlv  = (const float*)d_in[9];
    const float* blv  = (const float*)d_in[10];
    const int*   mask = (const int*)  d_in[11];
    float* out = (float*)d_out;

    void *pHT = nullptr, *pY = nullptr, *pX = nullptr;
    cudaGetSymbolAddress(&pHT, g_hT);
    cudaGetSymbolAddress(&pY,  g_y);
    cudaGetSymbolAddress(&pX,  g_X16);
    float* dY  = (float*)pY;
    float* dHT = (float*)pHT;
    __half* dX = (__half*)pX;
    cudaFuncSetAttribute(k_mma, cudaFuncAttributeMaxDynamicSharedMemorySize, SMEM_DYN);

    const int M = B_ * KS_;   // 256
    const int XN8 = B_ * L_ * D_ / 8;

    k_bounds<<<B_, 256>>>(mask);
    k_prepW<<<dim3(H_ / 32, D_ / 32), dim3(32, 8)>>>(Wp);
    k_prepX<<<XN8 / 256, 256>>>(tgt, dX);                        // stream 0
    k_prepX<<<XN8 / 256, 256>>>(dec, dX + (size_t)B_ * L_ * D_); // stream 1

    dim3 g1(H_ / TN_, KS_, B_ * 2);
    k_mma<<<g1, 256, SMEM_DYN>>>(bp, araw);
    k_scan<<<(B_ * H_) / 256, 256>>>(araw);

    k_fill_bias<<<(M * H_ / 4 + 255) / 256, 256>>>(dY, bout, H_ / 4, M * H_ / 4);
    k_gemm_splitk<<<dim3(H_ / 64, M / 32, 4), 256>>>(dHT, Wout, dY, M, H_, H_, 4);
    k_silu<<<(M * H_ + 255) / 256, 256>>>(dY, M * H_);

    float* outMu = out;
    float* outLv = out + (size_t)M * LAT_;
    k_fill_bias<<<(M * LAT_ / 4 + 255) / 256, 256>>>(outMu, bmu, LAT_ / 4, M * LAT_ / 4);
    k_fill_bias<<<(M * LAT_ / 4 + 255) / 256, 256>>>(outLv, blv, LAT_ / 4, M * LAT_ / 4);
    k_gemm_splitk<<<dim3(LAT_ / 64, M / 32, 4), 256>>>(dY, Wmu, outMu, M, LAT_, H_, 4);
    k_gemm_splitk<<<dim3(LAT_ / 64, M / 32, 4), 256>>>(dY, Wlv, outLv, M, LAT_, H_, 4);
}